// round 2
// baseline (speedup 1.0000x reference)
#include <cuda_runtime.h>
#include <cstdint>
#include <cstddef>

#define B 256
#define L 2048
#define H 128
#define V 32000
#define BL (B * L)
#define TOK 128   // tokens per encode block

typedef unsigned long long u64;

// Packed dual-FMA: d = a*b + c elementwise on float2 (sm_100+ f32x2 pipe).
__device__ __forceinline__ float2 ffma2(float2 a, float2 b, float2 c) {
    float2 d;
    asm("fma.rn.f32x2 %0, %1, %2, %3;"
        : "=l"(*(u64*)&d)
        : "l"(*(u64*)&a), "l"(*(u64*)&b), "l"(*(u64*)&c));
    return d;
}

// Scratch (no cudaMalloc allowed): device globals.
__device__ float g_h[(size_t)BL * H];   // 256 MB: encoded h_all [B,L,H]
__device__ float g_r[B * H];            // r = M_fin @ h_last
__device__ float g_rp[B * H];           // rp = r @ Wrp + brp

// ---------------------------------------------------------------------------
// Encode: h_all = LN(e + relu(e@W1+b1)@W2 + b2) * gamma + beta
// Block = 256 threads, 128 tokens. SMEM: e[128][128] (64KB) + h1[128][256] (128KB).
// All GEMM FMAs packed as f32x2 along output columns.
// ---------------------------------------------------------------------------
__global__ void __launch_bounds__(256, 1) encode_kernel(
    const int* __restrict__ seq, const float* __restrict__ embed,
    const float* __restrict__ W1, const float* __restrict__ b1,
    const float* __restrict__ W2, const float* __restrict__ b2,
    const float* __restrict__ gamma, const float* __restrict__ beta)
{
    extern __shared__ float sm[];
    float* e_sm  = sm;             // [TOK][H]
    float* h1_sm = sm + TOK * H;   // [TOK][2H]
    __shared__ int toks[TOK];

    const int t = threadIdx.x;
    const int tile0 = blockIdx.x * TOK;

    if (t < TOK) toks[t] = seq[tile0 + t];
    __syncthreads();

    // Gather embeddings: coalesced over the H dimension.
    #pragma unroll
    for (int i = 0; i < (TOK * H) / 256; i++) {
        int idx = i * 256 + t;
        int m = idx >> 7;
        int k = idx & (H - 1);
        e_sm[idx] = embed[(size_t)toks[m] * H + k];
    }
    __syncthreads();

    const int tx = t & 31;       // lane
    const int ty = t >> 5;       // warp 0..7
    const int m0 = ty * 16;      // 16 tokens per warp

    // ---------------- GEMM1: h1 = relu(e @ W1 + b1), N=256, K=128 ----------
    {
        const int n0 = tx * 8;
        float2 acc[16][4];   // col-pairs (n0+2j, n0+2j+1)
        #pragma unroll
        for (int i = 0; i < 16; i++)
            #pragma unroll
            for (int j = 0; j < 4; j++) acc[i][j] = make_float2(0.f, 0.f);

        #pragma unroll 2
        for (int k = 0; k < H; k++) {
            float4 w0 = *(const float4*)(W1 + (size_t)k * 256 + n0);
            float4 w1 = *(const float4*)(W1 + (size_t)k * 256 + n0 + 4);
            const float2* wp0 = reinterpret_cast<const float2*>(&w0);
            const float2* wp1 = reinterpret_cast<const float2*>(&w1);
            #pragma unroll
            for (int i = 0; i < 16; i++) {
                float ev = e_sm[(m0 + i) * H + k];   // broadcast LDS
                float2 ev2 = make_float2(ev, ev);
                acc[i][0] = ffma2(ev2, wp0[0], acc[i][0]);
                acc[i][1] = ffma2(ev2, wp0[1], acc[i][1]);
                acc[i][2] = ffma2(ev2, wp1[0], acc[i][2]);
                acc[i][3] = ffma2(ev2, wp1[1], acc[i][3]);
            }
        }
        float4 bb0 = *(const float4*)(b1 + n0);
        float4 bb1 = *(const float4*)(b1 + n0 + 4);
        #pragma unroll
        for (int i = 0; i < 16; i++) {
            float4 r0, r1;
            r0.x = fmaxf(acc[i][0].x + bb0.x, 0.f);
            r0.y = fmaxf(acc[i][0].y + bb0.y, 0.f);
            r0.z = fmaxf(acc[i][1].x + bb0.z, 0.f);
            r0.w = fmaxf(acc[i][1].y + bb0.w, 0.f);
            r1.x = fmaxf(acc[i][2].x + bb1.x, 0.f);
            r1.y = fmaxf(acc[i][2].y + bb1.y, 0.f);
            r1.z = fmaxf(acc[i][3].x + bb1.z, 0.f);
            r1.w = fmaxf(acc[i][3].y + bb1.w, 0.f);
            *(float4*)(h1_sm + (m0 + i) * 256 + n0)     = r0;
            *(float4*)(h1_sm + (m0 + i) * 256 + n0 + 4) = r1;
        }
    }
    __syncthreads();

    // ---------------- GEMM2: ff = h1 @ W2 + b2, N=128, K=256 ---------------
    const int c0 = tx * 4;
    float2 acc2[16][2];
    #pragma unroll
    for (int i = 0; i < 16; i++) {
        acc2[i][0] = make_float2(0.f, 0.f);
        acc2[i][1] = make_float2(0.f, 0.f);
    }

    #pragma unroll 2
    for (int k = 0; k < 2 * H; k++) {
        float4 w = *(const float4*)(W2 + (size_t)k * H + c0);
        const float2* wp = reinterpret_cast<const float2*>(&w);
        #pragma unroll
        for (int i = 0; i < 16; i++) {
            float hv = h1_sm[(m0 + i) * 256 + k];   // broadcast LDS
            float2 h2 = make_float2(hv, hv);
            acc2[i][0] = ffma2(h2, wp[0], acc2[i][0]);
            acc2[i][1] = ffma2(h2, wp[1], acc2[i][1]);
        }
    }

    // ---------------- residual + LayerNorm + write --------------------------
    const float4 gv  = *(const float4*)(gamma + c0);
    const float4 bv  = *(const float4*)(beta + c0);
    const float4 b2v = *(const float4*)(b2 + c0);
    #pragma unroll
    for (int i = 0; i < 16; i++) {
        int m = m0 + i;
        const float4 ev = *(const float4*)(e_sm + m * H + c0);
        float y0 = acc2[i][0].x + b2v.x + ev.x;
        float y1 = acc2[i][0].y + b2v.y + ev.y;
        float y2 = acc2[i][1].x + b2v.z + ev.z;
        float y3 = acc2[i][1].y + b2v.w + ev.w;
        float s = (y0 + y1) + (y2 + y3);
        float q = y0 * y0 + y1 * y1 + y2 * y2 + y3 * y3;
        #pragma unroll
        for (int o = 16; o; o >>= 1) {
            s += __shfl_xor_sync(0xffffffffu, s, o);
            q += __shfl_xor_sync(0xffffffffu, q, o);
        }
        float mu  = s * (1.0f / H);
        float var = q * (1.0f / H) - mu * mu;
        float inv = rsqrtf(var + 1e-5f);
        float4 o4;
        o4.x = (y0 - mu) * inv * gv.x + bv.x;
        o4.y = (y1 - mu) * inv * gv.y + bv.y;
        o4.z = (y2 - mu) * inv * gv.z + bv.z;
        o4.w = (y3 - mu) * inv * gv.w + bv.w;
        *(float4*)(g_h + (size_t)(tile0 + m) * H + c0) = o4;
    }
}

// ---------------------------------------------------------------------------
// Scan: one CTA per batch. Thread i owns M row i as float2[64] in registers.
// 2047 sequential delta-rule steps, all FMAs packed f32x2.
// ---------------------------------------------------------------------------
__global__ void __launch_bounds__(128, 2) scan_kernel()
{
    const int b = blockIdx.x;
    const int tid = threadIdx.x;
    const int lane = tid & 31;
    const int wid = tid >> 5;

    __shared__ float ks[2][H];
    __shared__ float red_kk[4];
    __shared__ float red_ee[4];

    float2 Mr[64];
    #pragma unroll
    for (int q = 0; q < 64; q++) Mr[q] = make_float2(0.f, 0.f);

    const float* hb = g_h + (size_t)b * L * H;
    float kv_next = hb[tid];   // k_0

    for (int t = 0; t < L - 1; t++) {
        const int buf = t & 1;
        const float kv = kv_next;
        ks[buf][tid] = kv;

        // kk = ||k||^2 (block reduce)
        float p = kv * kv;
        #pragma unroll
        for (int o = 16; o; o >>= 1) p += __shfl_xor_sync(0xffffffffu, p, o);
        if (lane == 0) red_kk[wid] = p;
        __syncthreads();                                   // BAR1

        kv_next = hb[(size_t)(t + 1) * H + tid];           // prefetch (t=2046 -> h_last)
        const float kk = (red_kk[0] + red_kk[1]) + (red_kk[2] + red_kk[3]);

        // vp_i = M_i . k   (4 packed accumulator chains)
        const float4* k4 = (const float4*)ks[buf];
        float2 a0 = make_float2(0.f, 0.f), a1 = a0, a2 = a0, a3 = a0;
        #pragma unroll
        for (int q = 0; q < 32; q += 2) {
            float4 ka = k4[q];
            float4 kb = k4[q + 1];
            const float2* kap = reinterpret_cast<const float2*>(&ka);
            const float2* kbp = reinterpret_cast<const float2*>(&kb);
            a0 = ffma2(Mr[2 * q + 0], kap[0], a0);
            a1 = ffma2(Mr[2 * q + 1], kap[1], a1);
            a2 = ffma2(Mr[2 * q + 2], kbp[0], a2);
            a3 = ffma2(Mr[2 * q + 3], kbp[1], a3);
        }
        const float vp = ((a0.x + a0.y) + (a1.x + a1.y))
                       + ((a2.x + a2.y) + (a3.x + a3.y));
        const float err = kv - vp / (kk + 1e-6f);

        // ee = ||err||^2 (block reduce)
        float pe = err * err;
        #pragma unroll
        for (int o = 16; o; o >>= 1) pe += __shfl_xor_sync(0xffffffffu, pe, o);
        if (lane == 0) red_ee[wid] = pe;
        __syncthreads();                                   // BAR2
        const float ee = (red_ee[0] + red_ee[1]) + (red_ee[2] + red_ee[3]);

        // gate = ||err|| > 0.4*||v||   (v = k  =>  compare squares)
        if (ee > 0.16f * kk) {                              // uniform branch
            const float2 e2 = make_float2(err, err);
            #pragma unroll
            for (int q = 0; q < 32; q++) {
                float4 kq = k4[q];
                const float2* kp = reinterpret_cast<const float2*>(&kq);
                Mr[2 * q + 0] = ffma2(e2, kp[0], Mr[2 * q + 0]);
                Mr[2 * q + 1] = ffma2(e2, kp[1], Mr[2 * q + 1]);
            }
        }
    }

    // Epilogue: r_i = M_i . h_last  (kv_next holds h_last[tid])
    ks[1][tid] = kv_next;
    __syncthreads();
    const float4* k4 = (const float4*)ks[1];
    float2 a0 = make_float2(0.f, 0.f), a1 = a0, a2 = a0, a3 = a0;
    #pragma unroll
    for (int q = 0; q < 32; q += 2) {
        float4 ka = k4[q];
        float4 kb = k4[q + 1];
        const float2* kap = reinterpret_cast<const float2*>(&ka);
        const float2* kbp = reinterpret_cast<const float2*>(&kb);
        a0 = ffma2(Mr[2 * q + 0], kap[0], a0);
        a1 = ffma2(Mr[2 * q + 1], kap[1], a1);
        a2 = ffma2(Mr[2 * q + 2], kbp[0], a2);
        a3 = ffma2(Mr[2 * q + 3], kbp[1], a3);
    }
    g_r[b * H + tid] = ((a0.x + a0.y) + (a1.x + a1.y))
                     + ((a2.x + a2.y) + (a3.x + a3.y));
}

// ---------------------------------------------------------------------------
// rp = r @ Wrp + brp   (tiny: 256 blocks x 128 threads)
// ---------------------------------------------------------------------------
__global__ void rp_kernel(const float* __restrict__ Wrp, const float* __restrict__ brp)
{
    const int b = blockIdx.x;
    const int i = threadIdx.x;
    __shared__ float rb[H];
    rb[i] = g_r[b * H + i];
    __syncthreads();
    float acc = brp[i];
    #pragma unroll 8
    for (int j = 0; j < H; j++) acc += rb[j] * Wrp[j * H + i];
    g_rp[b * H + i] = acc;
}

// ---------------------------------------------------------------------------
// out = rp @ Wout + bout.  Block: 256 thr, tile 64 batches x 128 vocab.
// ---------------------------------------------------------------------------
__global__ void __launch_bounds__(256) out_kernel(
    const float* __restrict__ Wout, const float* __restrict__ bout,
    float* __restrict__ out)
{
    __shared__ float rp_sm[64 * H];   // 32 KB
    const int t = threadIdx.x;
    const int v0 = blockIdx.x * 128;
    const int b0 = blockIdx.y * 64;

    #pragma unroll
    for (int i = 0; i < 32; i++) {
        int idx = i * 256 + t;
        rp_sm[idx] = g_rp[b0 * H + idx];
    }
    __syncthreads();

    const int tx = t & 31;
    const int ty = t >> 5;
    const int m0 = ty * 8;
    const int n  = v0 + tx * 4;

    float2 acc[8][2];
    #pragma unroll
    for (int i = 0; i < 8; i++) {
        acc[i][0] = make_float2(0.f, 0.f);
        acc[i][1] = make_float2(0.f, 0.f);
    }

    #pragma unroll 2
    for (int k = 0; k < H; k++) {
        float4 w = *(const float4*)(Wout + (size_t)k * V + n);
        const float2* wp = reinterpret_cast<const float2*>(&w);
        #pragma unroll
        for (int i = 0; i < 8; i++) {
            float hv = rp_sm[(m0 + i) * H + k];   // broadcast LDS
            float2 h2 = make_float2(hv, hv);
            acc[i][0] = ffma2(h2, wp[0], acc[i][0]);
            acc[i][1] = ffma2(h2, wp[1], acc[i][1]);
        }
    }
    const float4 bo = *(const float4*)(bout + n);
    #pragma unroll
    for (int i = 0; i < 8; i++) {
        float4 o;
        o.x = acc[i][0].x + bo.x; o.y = acc[i][0].y + bo.y;
        o.z = acc[i][1].x + bo.z; o.w = acc[i][1].y + bo.w;
        *(float4*)(out + (size_t)(b0 + m0 + i) * V + n) = o;
    }
}

// ---------------------------------------------------------------------------
extern "C" void kernel_launch(void* const* d_in, const int* in_sizes, int n_in,
                              void* d_out, int out_size)
{
    const int*   seq   = (const int*)  d_in[0];
    const float* embed = (const float*)d_in[1];
    const float* W1    = (const float*)d_in[2];
    const float* b1    = (const float*)d_in[3];
    const float* W2    = (const float*)d_in[4];
    const float* b2    = (const float*)d_in[5];
    const float* gamma = (const float*)d_in[6];
    const float* beta  = (const float*)d_in[7];
    const float* Wrp   = (const float*)d_in[8];
    const float* brp   = (const float*)d_in[9];
    const float* Wout  = (const float*)d_in[10];
    const float* bout  = (const float*)d_in[11];
    float* out = (float*)d_out;

    const size_t enc_smem = (size_t)(TOK * H + TOK * 2 * H) * sizeof(float); // 196608
    cudaFuncSetAttribute(encode_kernel,
                         cudaFuncAttributeMaxDynamicSharedMemorySize,
                         (int)enc_smem);

    encode_kernel<<<BL / TOK, 256, enc_smem>>>(seq, embed, W1, b1, W2, b2, gamma, beta);
    scan_kernel<<<B, 128>>>();
    rp_kernel<<<B, H>>>(Wrp, brp);
    dim3 og(V / 128, B / 64);
    out_kernel<<<og, 256>>>(Wout, bout, out);
}

// round 3
// speedup vs baseline: 1.0385x; 1.0385x over previous
#include <cuda_runtime.h>
#include <cstdint>
#include <cstddef>

#define B 256
#define L 2048
#define H 128
#define V 32000
#define BL (B * L)
#define TOK 128   // tokens per encode block

typedef unsigned long long u64;

// Packed dual-FMA: d = a*b + c elementwise on float2 (sm_100+ f32x2 pipe).
__device__ __forceinline__ float2 ffma2(float2 a, float2 b, float2 c) {
    float2 d;
    asm("fma.rn.f32x2 %0, %1, %2, %3;"
        : "=l"(*(u64*)&d)
        : "l"(*(u64*)&a), "l"(*(u64*)&b), "l"(*(u64*)&c));
    return d;
}

// Scratch (no cudaMalloc allowed): device globals.
__device__ float g_h[(size_t)BL * H];   // 256 MB: encoded h_all [B,L,H]
__device__ float g_r[B * H];            // r = M_fin @ h_last
__device__ float g_rp[B * H];           // rp = r @ Wrp + brp

// ---------------------------------------------------------------------------
// Encode: h_all = LN(e + relu(e@W1+b1)@W2 + b2) * gamma + beta
// Block = 256 threads, 128 tokens. SMEM: e[128][128] (64KB) + h1[128][256] (128KB).
// All GEMM FMAs packed as f32x2 along output columns.
// ---------------------------------------------------------------------------
__global__ void __launch_bounds__(256, 1) encode_kernel(
    const int* __restrict__ seq, const float* __restrict__ embed,
    const float* __restrict__ W1, const float* __restrict__ b1,
    const float* __restrict__ W2, const float* __restrict__ b2,
    const float* __restrict__ gamma, const float* __restrict__ beta)
{
    extern __shared__ float sm[];
    float* e_sm  = sm;             // [TOK][H]
    float* h1_sm = sm + TOK * H;   // [TOK][2H]
    __shared__ int toks[TOK];

    const int t = threadIdx.x;
    const int tile0 = blockIdx.x * TOK;

    if (t < TOK) toks[t] = seq[tile0 + t];
    __syncthreads();

    // Gather embeddings: coalesced over the H dimension.
    #pragma unroll
    for (int i = 0; i < (TOK * H) / 256; i++) {
        int idx = i * 256 + t;
        int m = idx >> 7;
        int k = idx & (H - 1);
        e_sm[idx] = embed[(size_t)toks[m] * H + k];
    }
    __syncthreads();

    const int tx = t & 31;       // lane
    const int ty = t >> 5;       // warp 0..7
    const int m0 = ty * 16;      // 16 tokens per warp

    // ---------------- GEMM1: h1 = relu(e @ W1 + b1), N=256, K=128 ----------
    {
        const int n0 = tx * 8;
        float2 acc[16][4];   // col-pairs (n0+2j, n0+2j+1)
        #pragma unroll
        for (int i = 0; i < 16; i++)
            #pragma unroll
            for (int j = 0; j < 4; j++) acc[i][j] = make_float2(0.f, 0.f);

        #pragma unroll 2
        for (int k = 0; k < H; k++) {
            float4 w0 = *(const float4*)(W1 + (size_t)k * 256 + n0);
            float4 w1 = *(const float4*)(W1 + (size_t)k * 256 + n0 + 4);
            const float2* wp0 = reinterpret_cast<const float2*>(&w0);
            const float2* wp1 = reinterpret_cast<const float2*>(&w1);
            #pragma unroll
            for (int i = 0; i < 16; i++) {
                float ev = e_sm[(m0 + i) * H + k];   // broadcast LDS
                float2 ev2 = make_float2(ev, ev);
                acc[i][0] = ffma2(ev2, wp0[0], acc[i][0]);
                acc[i][1] = ffma2(ev2, wp0[1], acc[i][1]);
                acc[i][2] = ffma2(ev2, wp1[0], acc[i][2]);
                acc[i][3] = ffma2(ev2, wp1[1], acc[i][3]);
            }
        }
        float4 bb0 = *(const float4*)(b1 + n0);
        float4 bb1 = *(const float4*)(b1 + n0 + 4);
        #pragma unroll
        for (int i = 0; i < 16; i++) {
            float4 r0, r1;
            r0.x = fmaxf(acc[i][0].x + bb0.x, 0.f);
            r0.y = fmaxf(acc[i][0].y + bb0.y, 0.f);
            r0.z = fmaxf(acc[i][1].x + bb0.z, 0.f);
            r0.w = fmaxf(acc[i][1].y + bb0.w, 0.f);
            r1.x = fmaxf(acc[i][2].x + bb1.x, 0.f);
            r1.y = fmaxf(acc[i][2].y + bb1.y, 0.f);
            r1.z = fmaxf(acc[i][3].x + bb1.z, 0.f);
            r1.w = fmaxf(acc[i][3].y + bb1.w, 0.f);
            *(float4*)(h1_sm + (m0 + i) * 256 + n0)     = r0;
            *(float4*)(h1_sm + (m0 + i) * 256 + n0 + 4) = r1;
        }
    }
    __syncthreads();

    // ---------------- GEMM2: ff = h1 @ W2 + b2, N=128, K=256 ---------------
    const int c0 = tx * 4;
    float2 acc2[16][2];
    #pragma unroll
    for (int i = 0; i < 16; i++) {
        acc2[i][0] = make_float2(0.f, 0.f);
        acc2[i][1] = make_float2(0.f, 0.f);
    }

    #pragma unroll 2
    for (int k = 0; k < 2 * H; k++) {
        float4 w = *(const float4*)(W2 + (size_t)k * H + c0);
        const float2* wp = reinterpret_cast<const float2*>(&w);
        #pragma unroll
        for (int i = 0; i < 16; i++) {
            float hv = h1_sm[(m0 + i) * 256 + k];   // broadcast LDS
            float2 h2 = make_float2(hv, hv);
            acc2[i][0] = ffma2(h2, wp[0], acc2[i][0]);
            acc2[i][1] = ffma2(h2, wp[1], acc2[i][1]);
        }
    }

    // ---------------- residual + LayerNorm + write --------------------------
    const float4 gv  = *(const float4*)(gamma + c0);
    const float4 bv  = *(const float4*)(beta + c0);
    const float4 b2v = *(const float4*)(b2 + c0);
    #pragma unroll
    for (int i = 0; i < 16; i++) {
        int m = m0 + i;
        const float4 ev = *(const float4*)(e_sm + m * H + c0);
        float y0 = acc2[i][0].x + b2v.x + ev.x;
        float y1 = acc2[i][0].y + b2v.y + ev.y;
        float y2 = acc2[i][1].x + b2v.z + ev.z;
        float y3 = acc2[i][1].y + b2v.w + ev.w;
        float s = (y0 + y1) + (y2 + y3);
        float q = y0 * y0 + y1 * y1 + y2 * y2 + y3 * y3;
        #pragma unroll
        for (int o = 16; o; o >>= 1) {
            s += __shfl_xor_sync(0xffffffffu, s, o);
            q += __shfl_xor_sync(0xffffffffu, q, o);
        }
        float mu  = s * (1.0f / H);
        float var = q * (1.0f / H) - mu * mu;
        float inv = rsqrtf(var + 1e-5f);
        float4 o4;
        o4.x = (y0 - mu) * inv * gv.x + bv.x;
        o4.y = (y1 - mu) * inv * gv.y + bv.y;
        o4.z = (y2 - mu) * inv * gv.z + bv.z;
        o4.w = (y3 - mu) * inv * gv.w + bv.w;
        *(float4*)(g_h + (size_t)(tile0 + m) * H + c0) = o4;
    }
}

// ---------------------------------------------------------------------------
// Scan: one CTA per batch. Thread i owns M row i as float2[64] in registers.
// 2047 sequential delta-rule steps, all FMAs packed f32x2.
// ---------------------------------------------------------------------------
__global__ void __launch_bounds__(128, 2) scan_kernel()
{
    const int b = blockIdx.x;
    const int tid = threadIdx.x;
    const int lane = tid & 31;
    const int wid = tid >> 5;

    __shared__ float ks[2][H];
    __shared__ float red_kk[4];
    __shared__ float red_ee[4];

    float2 Mr[64];
    #pragma unroll
    for (int q = 0; q < 64; q++) Mr[q] = make_float2(0.f, 0.f);

    const float* hb = g_h + (size_t)b * L * H;
    float kv_next = hb[tid];   // k_0

    for (int t = 0; t < L - 1; t++) {
        const int buf = t & 1;
        const float kv = kv_next;
        ks[buf][tid] = kv;

        // kk = ||k||^2 (block reduce)
        float p = kv * kv;
        #pragma unroll
        for (int o = 16; o; o >>= 1) p += __shfl_xor_sync(0xffffffffu, p, o);
        if (lane == 0) red_kk[wid] = p;
        __syncthreads();                                   // BAR1

        kv_next = hb[(size_t)(t + 1) * H + tid];           // prefetch (t=2046 -> h_last)
        const float kk = (red_kk[0] + red_kk[1]) + (red_kk[2] + red_kk[3]);

        // vp_i = M_i . k   (4 packed accumulator chains)
        const float4* k4 = (const float4*)ks[buf];
        float2 a0 = make_float2(0.f, 0.f), a1 = a0, a2 = a0, a3 = a0;
        #pragma unroll
        for (int q = 0; q < 32; q += 2) {
            float4 ka = k4[q];
            float4 kb = k4[q + 1];
            const float2* kap = reinterpret_cast<const float2*>(&ka);
            const float2* kbp = reinterpret_cast<const float2*>(&kb);
            a0 = ffma2(Mr[2 * q + 0], kap[0], a0);
            a1 = ffma2(Mr[2 * q + 1], kap[1], a1);
            a2 = ffma2(Mr[2 * q + 2], kbp[0], a2);
            a3 = ffma2(Mr[2 * q + 3], kbp[1], a3);
        }
        const float vp = ((a0.x + a0.y) + (a1.x + a1.y))
                       + ((a2.x + a2.y) + (a3.x + a3.y));
        const float err = kv - vp / (kk + 1e-6f);

        // ee = ||err||^2 (block reduce)
        float pe = err * err;
        #pragma unroll
        for (int o = 16; o; o >>= 1) pe += __shfl_xor_sync(0xffffffffu, pe, o);
        if (lane == 0) red_ee[wid] = pe;
        __syncthreads();                                   // BAR2
        const float ee = (red_ee[0] + red_ee[1]) + (red_ee[2] + red_ee[3]);

        // gate = ||err|| > 0.4*||v||   (v = k  =>  compare squares)
        if (ee > 0.16f * kk) {                              // uniform branch
            const float2 e2 = make_float2(err, err);
            #pragma unroll
            for (int q = 0; q < 32; q++) {
                float4 kq = k4[q];
                const float2* kp = reinterpret_cast<const float2*>(&kq);
                Mr[2 * q + 0] = ffma2(e2, kp[0], Mr[2 * q + 0]);
                Mr[2 * q + 1] = ffma2(e2, kp[1], Mr[2 * q + 1]);
            }
        }
    }

    // Epilogue: r_i = M_i . h_last  (kv_next holds h_last[tid])
    ks[1][tid] = kv_next;
    __syncthreads();
    const float4* k4 = (const float4*)ks[1];
    float2 a0 = make_float2(0.f, 0.f), a1 = a0, a2 = a0, a3 = a0;
    #pragma unroll
    for (int q = 0; q < 32; q += 2) {
        float4 ka = k4[q];
        float4 kb = k4[q + 1];
        const float2* kap = reinterpret_cast<const float2*>(&ka);
        const float2* kbp = reinterpret_cast<const float2*>(&kb);
        a0 = ffma2(Mr[2 * q + 0], kap[0], a0);
        a1 = ffma2(Mr[2 * q + 1], kap[1], a1);
        a2 = ffma2(Mr[2 * q + 2], kbp[0], a2);
        a3 = ffma2(Mr[2 * q + 3], kbp[1], a3);
    }
    g_r[b * H + tid] = ((a0.x + a0.y) + (a1.x + a1.y))
                     + ((a2.x + a2.y) + (a3.x + a3.y));
}

// ---------------------------------------------------------------------------
// rp = r @ Wrp + brp   (tiny: 256 blocks x 128 threads)
// ---------------------------------------------------------------------------
__global__ void rp_kernel(const float* __restrict__ Wrp, const float* __restrict__ brp)
{
    const int b = blockIdx.x;
    const int i = threadIdx.x;
    __shared__ float rb[H];
    rb[i] = g_r[b * H + i];
    __syncthreads();
    float acc = brp[i];
    #pragma unroll 8
    for (int j = 0; j < H; j++) acc += rb[j] * Wrp[j * H + i];
    g_rp[b * H + i] = acc;
}

// ---------------------------------------------------------------------------
// out = rp @ Wout + bout.  Block: 256 thr, tile 64 batches x 128 vocab.
// ---------------------------------------------------------------------------
__global__ void __launch_bounds__(256) out_kernel(
    const float* __restrict__ Wout, const float* __restrict__ bout,
    float* __restrict__ out)
{
    __shared__ float rp_sm[64 * H];   // 32 KB
    const int t = threadIdx.x;
    const int v0 = blockIdx.x * 128;
    const int b0 = blockIdx.y * 64;

    #pragma unroll
    for (int i = 0; i < 32; i++) {
        int idx = i * 256 + t;
        rp_sm[idx] = g_rp[b0 * H + idx];
    }
    __syncthreads();

    const int tx = t & 31;
    const int ty = t >> 5;
    const int m0 = ty * 8;
    const int n  = v0 + tx * 4;

    float2 acc[8][2];
    #pragma unroll
    for (int i = 0; i < 8; i++) {
        acc[i][0] = make_float2(0.f, 0.f);
        acc[i][1] = make_float2(0.f, 0.f);
    }

    #pragma unroll 2
    for (int k = 0; k < H; k++) {
        float4 w = *(const float4*)(Wout + (size_t)k * V + n);
        const float2* wp = reinterpret_cast<const float2*>(&w);
        #pragma unroll
        for (int i = 0; i < 8; i++) {
            float hv = rp_sm[(m0 + i) * H + k];   // broadcast LDS
            float2 h2 = make_float2(hv, hv);
            acc[i][0] = ffma2(h2, wp[0], acc[i][0]);
            acc[i][1] = ffma2(h2, wp[1], acc[i][1]);
        }
    }
    const float4 bo = *(const float4*)(bout + n);
    #pragma unroll
    for (int i = 0; i < 8; i++) {
        float4 o;
        o.x = acc[i][0].x + bo.x; o.y = acc[i][0].y + bo.y;
        o.z = acc[i][1].x + bo.z; o.w = acc[i][1].y + bo.w;
        *(float4*)(out + (size_t)(b0 + m0 + i) * V + n) = o;
    }
}

// ---------------------------------------------------------------------------
extern "C" void kernel_launch(void* const* d_in, const int* in_sizes, int n_in,
                              void* d_out, int out_size)
{
    const int*   seq   = (const int*)  d_in[0];
    const float* embed = (const float*)d_in[1];
    const float* W1    = (const float*)d_in[2];
    const float* b1    = (const float*)d_in[3];
    const float* W2    = (const float*)d_in[4];
    const float* b2    = (const float*)d_in[5];
    const float* gamma = (const float*)d_in[6];
    const float* beta  = (const float*)d_in[7];
    const float* Wrp   = (const float*)d_in[8];
    const float* brp   = (const float*)d_in[9];
    const float* Wout  = (const float*)d_in[10];
    const float* bout  = (const float*)d_in[11];
    float* out = (float*)d_out;

    const size_t enc_smem = (size_t)(TOK * H + TOK * 2 * H) * sizeof(float); // 196608
    cudaFuncSetAttribute(encode_kernel,
                         cudaFuncAttributeMaxDynamicSharedMemorySize,
                         (int)enc_smem);

    encode_kernel<<<BL / TOK, 256, enc_smem>>>(seq, embed, W1, b1, W2, b2, gamma, beta);
    scan_kernel<<<B, 128>>>();
    rp_kernel<<<B, H>>>(Wrp, brp);
    dim3 og(V / 128, B / 64);
    out_kernel<<<og, 256>>>(Wout, bout, out);
}

// round 4
// speedup vs baseline: 1.0407x; 1.0021x over previous
#include <cuda_runtime.h>
#include <cstdint>
#include <cstddef>

#define B 256
#define L 2048
#define H 128
#define V 32000
#define BL (B * L)
#define TOK 128   // tokens per encode block

typedef unsigned long long u64;

// Packed dual-FMA: d = a*b + c elementwise on float2 (sm_100+ f32x2 pipe).
__device__ __forceinline__ float2 ffma2(float2 a, float2 b, float2 c) {
    float2 d;
    asm("fma.rn.f32x2 %0, %1, %2, %3;"
        : "=l"(*(u64*)&d)
        : "l"(*(u64*)&a), "l"(*(u64*)&b), "l"(*(u64*)&c));
    return d;
}

// Scratch (no cudaMalloc allowed): device globals.
__device__ float g_h[(size_t)BL * H];   // 256 MB: encoded h_all [B,L,H]
__device__ float g_r[B * H];            // r = M_fin @ h_last
__device__ float g_rp[B * H];           // rp = r @ Wrp + brp

// ---------------------------------------------------------------------------
// Encode: h_all = LN(e + relu(e@W1+b1)@W2 + b2) * gamma + beta
// Block = 256 threads, 128 tokens. SMEM: e[128][128] (64KB) + h1[128][256] (128KB).
// All GEMM FMAs packed as f32x2 along output columns.
// ---------------------------------------------------------------------------
__global__ void __launch_bounds__(256, 1) encode_kernel(
    const int* __restrict__ seq, const float* __restrict__ embed,
    const float* __restrict__ W1, const float* __restrict__ b1,
    const float* __restrict__ W2, const float* __restrict__ b2,
    const float* __restrict__ gamma, const float* __restrict__ beta)
{
    extern __shared__ float sm[];
    float* e_sm  = sm;             // [TOK][H]
    float* h1_sm = sm + TOK * H;   // [TOK][2H]
    __shared__ int toks[TOK];

    const int t = threadIdx.x;
    const int tile0 = blockIdx.x * TOK;

    if (t < TOK) toks[t] = seq[tile0 + t];
    __syncthreads();

    // Gather embeddings: coalesced over the H dimension.
    #pragma unroll
    for (int i = 0; i < (TOK * H) / 256; i++) {
        int idx = i * 256 + t;
        int m = idx >> 7;
        int k = idx & (H - 1);
        e_sm[idx] = embed[(size_t)toks[m] * H + k];
    }
    __syncthreads();

    const int tx = t & 31;       // lane
    const int ty = t >> 5;       // warp 0..7
    const int m0 = ty * 16;      // 16 tokens per warp

    // ---------------- GEMM1: h1 = relu(e @ W1 + b1), N=256, K=128 ----------
    {
        const int n0 = tx * 8;
        float2 acc[16][4];   // col-pairs (n0+2j, n0+2j+1)
        #pragma unroll
        for (int i = 0; i < 16; i++)
            #pragma unroll
            for (int j = 0; j < 4; j++) acc[i][j] = make_float2(0.f, 0.f);

        #pragma unroll 2
        for (int k = 0; k < H; k++) {
            float4 w0 = *(const float4*)(W1 + (size_t)k * 256 + n0);
            float4 w1 = *(const float4*)(W1 + (size_t)k * 256 + n0 + 4);
            const float2* wp0 = reinterpret_cast<const float2*>(&w0);
            const float2* wp1 = reinterpret_cast<const float2*>(&w1);
            #pragma unroll
            for (int i = 0; i < 16; i++) {
                float ev = e_sm[(m0 + i) * H + k];   // broadcast LDS
                float2 ev2 = make_float2(ev, ev);
                acc[i][0] = ffma2(ev2, wp0[0], acc[i][0]);
                acc[i][1] = ffma2(ev2, wp0[1], acc[i][1]);
                acc[i][2] = ffma2(ev2, wp1[0], acc[i][2]);
                acc[i][3] = ffma2(ev2, wp1[1], acc[i][3]);
            }
        }
        float4 bb0 = *(const float4*)(b1 + n0);
        float4 bb1 = *(const float4*)(b1 + n0 + 4);
        #pragma unroll
        for (int i = 0; i < 16; i++) {
            float4 r0, r1;
            r0.x = fmaxf(acc[i][0].x + bb0.x, 0.f);
            r0.y = fmaxf(acc[i][0].y + bb0.y, 0.f);
            r0.z = fmaxf(acc[i][1].x + bb0.z, 0.f);
            r0.w = fmaxf(acc[i][1].y + bb0.w, 0.f);
            r1.x = fmaxf(acc[i][2].x + bb1.x, 0.f);
            r1.y = fmaxf(acc[i][2].y + bb1.y, 0.f);
            r1.z = fmaxf(acc[i][3].x + bb1.z, 0.f);
            r1.w = fmaxf(acc[i][3].y + bb1.w, 0.f);
            *(float4*)(h1_sm + (m0 + i) * 256 + n0)     = r0;
            *(float4*)(h1_sm + (m0 + i) * 256 + n0 + 4) = r1;
        }
    }
    __syncthreads();

    // ---------------- GEMM2: ff = h1 @ W2 + b2, N=128, K=256 ---------------
    const int c0 = tx * 4;
    float2 acc2[16][2];
    #pragma unroll
    for (int i = 0; i < 16; i++) {
        acc2[i][0] = make_float2(0.f, 0.f);
        acc2[i][1] = make_float2(0.f, 0.f);
    }

    #pragma unroll 2
    for (int k = 0; k < 2 * H; k++) {
        float4 w = *(const float4*)(W2 + (size_t)k * H + c0);
        const float2* wp = reinterpret_cast<const float2*>(&w);
        #pragma unroll
        for (int i = 0; i < 16; i++) {
            float hv = h1_sm[(m0 + i) * 256 + k];   // broadcast LDS
            float2 h2 = make_float2(hv, hv);
            acc2[i][0] = ffma2(h2, wp[0], acc2[i][0]);
            acc2[i][1] = ffma2(h2, wp[1], acc2[i][1]);
        }
    }

    // ---------------- residual + LayerNorm + write --------------------------
    const float4 gv  = *(const float4*)(gamma + c0);
    const float4 bv  = *(const float4*)(beta + c0);
    const float4 b2v = *(const float4*)(b2 + c0);
    #pragma unroll
    for (int i = 0; i < 16; i++) {
        int m = m0 + i;
        const float4 ev = *(const float4*)(e_sm + m * H + c0);
        float y0 = acc2[i][0].x + b2v.x + ev.x;
        float y1 = acc2[i][0].y + b2v.y + ev.y;
        float y2 = acc2[i][1].x + b2v.z + ev.z;
        float y3 = acc2[i][1].y + b2v.w + ev.w;
        float s = (y0 + y1) + (y2 + y3);
        float q = y0 * y0 + y1 * y1 + y2 * y2 + y3 * y3;
        #pragma unroll
        for (int o = 16; o; o >>= 1) {
            s += __shfl_xor_sync(0xffffffffu, s, o);
            q += __shfl_xor_sync(0xffffffffu, q, o);
        }
        float mu  = s * (1.0f / H);
        float var = q * (1.0f / H) - mu * mu;
        float inv = rsqrtf(var + 1e-5f);
        float4 o4;
        o4.x = (y0 - mu) * inv * gv.x + bv.x;
        o4.y = (y1 - mu) * inv * gv.y + bv.y;
        o4.z = (y2 - mu) * inv * gv.z + bv.z;
        o4.w = (y3 - mu) * inv * gv.w + bv.w;
        *(float4*)(g_h + (size_t)(tile0 + m) * H + c0) = o4;
    }
}

// ---------------------------------------------------------------------------
// Scan: one CTA per batch. Thread i owns M row i as float2[64] in registers.
// 2047 sequential delta-rule steps, all FMAs packed f32x2.
// ---------------------------------------------------------------------------
__global__ void __launch_bounds__(128, 2) scan_kernel()
{
    const int b = blockIdx.x;
    const int tid = threadIdx.x;
    const int lane = tid & 31;
    const int wid = tid >> 5;

    __shared__ float ks[2][H];
    __shared__ float red_kk[4];
    __shared__ float red_ee[4];

    float2 Mr[64];
    #pragma unroll
    for (int q = 0; q < 64; q++) Mr[q] = make_float2(0.f, 0.f);

    const float* hb = g_h + (size_t)b * L * H;
    float kv_next = hb[tid];   // k_0

    for (int t = 0; t < L - 1; t++) {
        const int buf = t & 1;
        const float kv = kv_next;
        ks[buf][tid] = kv;

        // kk = ||k||^2 (block reduce)
        float p = kv * kv;
        #pragma unroll
        for (int o = 16; o; o >>= 1) p += __shfl_xor_sync(0xffffffffu, p, o);
        if (lane == 0) red_kk[wid] = p;
        __syncthreads();                                   // BAR1

        kv_next = hb[(size_t)(t + 1) * H + tid];           // prefetch (t=2046 -> h_last)
        const float kk = (red_kk[0] + red_kk[1]) + (red_kk[2] + red_kk[3]);

        // vp_i = M_i . k   (4 packed accumulator chains)
        const float4* k4 = (const float4*)ks[buf];
        float2 a0 = make_float2(0.f, 0.f), a1 = a0, a2 = a0, a3 = a0;
        #pragma unroll
        for (int q = 0; q < 32; q += 2) {
            float4 ka = k4[q];
            float4 kb = k4[q + 1];
            const float2* kap = reinterpret_cast<const float2*>(&ka);
            const float2* kbp = reinterpret_cast<const float2*>(&kb);
            a0 = ffma2(Mr[2 * q + 0], kap[0], a0);
            a1 = ffma2(Mr[2 * q + 1], kap[1], a1);
            a2 = ffma2(Mr[2 * q + 2], kbp[0], a2);
            a3 = ffma2(Mr[2 * q + 3], kbp[1], a3);
        }
        const float vp = ((a0.x + a0.y) + (a1.x + a1.y))
                       + ((a2.x + a2.y) + (a3.x + a3.y));
        const float err = kv - vp / (kk + 1e-6f);

        // ee = ||err||^2 (block reduce)
        float pe = err * err;
        #pragma unroll
        for (int o = 16; o; o >>= 1) pe += __shfl_xor_sync(0xffffffffu, pe, o);
        if (lane == 0) red_ee[wid] = pe;
        __syncthreads();                                   // BAR2
        const float ee = (red_ee[0] + red_ee[1]) + (red_ee[2] + red_ee[3]);

        // gate = ||err|| > 0.4*||v||   (v = k  =>  compare squares)
        if (ee > 0.16f * kk) {                              // uniform branch
            const float2 e2 = make_float2(err, err);
            #pragma unroll
            for (int q = 0; q < 32; q++) {
                float4 kq = k4[q];
                const float2* kp = reinterpret_cast<const float2*>(&kq);
                Mr[2 * q + 0] = ffma2(e2, kp[0], Mr[2 * q + 0]);
                Mr[2 * q + 1] = ffma2(e2, kp[1], Mr[2 * q + 1]);
            }
        }
    }

    // Epilogue: r_i = M_i . h_last  (kv_next holds h_last[tid])
    ks[1][tid] = kv_next;
    __syncthreads();
    const float4* k4 = (const float4*)ks[1];
    float2 a0 = make_float2(0.f, 0.f), a1 = a0, a2 = a0, a3 = a0;
    #pragma unroll
    for (int q = 0; q < 32; q += 2) {
        float4 ka = k4[q];
        float4 kb = k4[q + 1];
        const float2* kap = reinterpret_cast<const float2*>(&ka);
        const float2* kbp = reinterpret_cast<const float2*>(&kb);
        a0 = ffma2(Mr[2 * q + 0], kap[0], a0);
        a1 = ffma2(Mr[2 * q + 1], kap[1], a1);
        a2 = ffma2(Mr[2 * q + 2], kbp[0], a2);
        a3 = ffma2(Mr[2 * q + 3], kbp[1], a3);
    }
    g_r[b * H + tid] = ((a0.x + a0.y) + (a1.x + a1.y))
                     + ((a2.x + a2.y) + (a3.x + a3.y));
}

// ---------------------------------------------------------------------------
// rp = r @ Wrp + brp   (tiny: 256 blocks x 128 threads)
// ---------------------------------------------------------------------------
__global__ void rp_kernel(const float* __restrict__ Wrp, const float* __restrict__ brp)
{
    const int b = blockIdx.x;
    const int i = threadIdx.x;
    __shared__ float rb[H];
    rb[i] = g_r[b * H + i];
    __syncthreads();
    float acc = brp[i];
    #pragma unroll 8
    for (int j = 0; j < H; j++) acc += rb[j] * Wrp[j * H + i];
    g_rp[b * H + i] = acc;
}

// ---------------------------------------------------------------------------
// out = rp @ Wout + bout.  Block: 256 thr, tile 64 batches x 128 vocab.
// ---------------------------------------------------------------------------
__global__ void __launch_bounds__(256) out_kernel(
    const float* __restrict__ Wout, const float* __restrict__ bout,
    float* __restrict__ out)
{
    __shared__ float rp_sm[64 * H];   // 32 KB
    const int t = threadIdx.x;
    const int v0 = blockIdx.x * 128;
    const int b0 = blockIdx.y * 64;

    #pragma unroll
    for (int i = 0; i < 32; i++) {
        int idx = i * 256 + t;
        rp_sm[idx] = g_rp[b0 * H + idx];
    }
    __syncthreads();

    const int tx = t & 31;
    const int ty = t >> 5;
    const int m0 = ty * 8;
    const int n  = v0 + tx * 4;

    float2 acc[8][2];
    #pragma unroll
    for (int i = 0; i < 8; i++) {
        acc[i][0] = make_float2(0.f, 0.f);
        acc[i][1] = make_float2(0.f, 0.f);
    }

    #pragma unroll 2
    for (int k = 0; k < H; k++) {
        float4 w = *(const float4*)(Wout + (size_t)k * V + n);
        const float2* wp = reinterpret_cast<const float2*>(&w);
        #pragma unroll
        for (int i = 0; i < 8; i++) {
            float hv = rp_sm[(m0 + i) * H + k];   // broadcast LDS
            float2 h2 = make_float2(hv, hv);
            acc[i][0] = ffma2(h2, wp[0], acc[i][0]);
            acc[i][1] = ffma2(h2, wp[1], acc[i][1]);
        }
    }
    const float4 bo = *(const float4*)(bout + n);
    #pragma unroll
    for (int i = 0; i < 8; i++) {
        float4 o;
        o.x = acc[i][0].x + bo.x; o.y = acc[i][0].y + bo.y;
        o.z = acc[i][1].x + bo.z; o.w = acc[i][1].y + bo.w;
        *(float4*)(out + (size_t)(b0 + m0 + i) * V + n) = o;
    }
}

// ---------------------------------------------------------------------------
extern "C" void kernel_launch(void* const* d_in, const int* in_sizes, int n_in,
                              void* d_out, int out_size)
{
    const int*   seq   = (const int*)  d_in[0];
    const float* embed = (const float*)d_in[1];
    const float* W1    = (const float*)d_in[2];
    const float* b1    = (const float*)d_in[3];
    const float* W2    = (const float*)d_in[4];
    const float* b2    = (const float*)d_in[5];
    const float* gamma = (const float*)d_in[6];
    const float* beta  = (const float*)d_in[7];
    const float* Wrp   = (const float*)d_in[8];
    const float* brp   = (const float*)d_in[9];
    const float* Wout  = (const float*)d_in[10];
    const float* bout  = (const float*)d_in[11];
    float* out = (float*)d_out;

    const size_t enc_smem = (size_t)(TOK * H + TOK * 2 * H) * sizeof(float); // 196608
    cudaFuncSetAttribute(encode_kernel,
                         cudaFuncAttributeMaxDynamicSharedMemorySize,
                         (int)enc_smem);

    encode_kernel<<<BL / TOK, 256, enc_smem>>>(seq, embed, W1, b1, W2, b2, gamma, beta);
    scan_kernel<<<B, 128>>>();
    rp_kernel<<<B, H>>>(Wrp, brp);
    dim3 og(V / 128, B / 64);
    out_kernel<<<og, 256>>>(Wout, bout, out);
}